// round 3
// baseline (speedup 1.0000x reference)
#include <cuda_runtime.h>
#include <cstdint>

// ---------------- problem constants ----------------
#define N_PTS   65536            // 16 * 64 * 64 points
#define KCODES  1024
#define DIM     64
#define NELEM   4194304          // 16*64*64*64 elements of quantized
#define HW      4096             // 64*64

// output layout: loss | quantized_st (NCHW) | perplexity | encodings [N, K]
#define OFF_LOSS 0
#define OFF_Q    1
#define OFF_PERP (1 + NELEM)         // 4194305
#define OFF_ENC  (OFF_PERP + 1)      // 4194306
#define ENC_FLOATS (N_PTS * KCODES)  // 67108864

// ---------------- device scratch (no allocation allowed) ----------------
__device__ float g_wt[DIM * KCODES];   // W transposed: wt[d*1024 + k]
__device__ float g_wnorm[KCODES];      // s2[k] = sum_d w^2, sequential fp32
__device__ int   g_idx[N_PTS];
__device__ float g_loss_sum;
__device__ int   g_hist[KCODES];

// ---------------- f32x2 helpers ----------------
__device__ __forceinline__ unsigned long long pack2(float v) {
    unsigned long long r;
    asm("mov.b64 %0, {%1, %1};" : "=l"(r) : "f"(v));
    return r;
}
__device__ __forceinline__ unsigned long long fma2(unsigned long long a,
                                                   unsigned long long b,
                                                   unsigned long long c) {
    unsigned long long d;
    asm("fma.rn.f32x2 %0, %1, %2, %3;" : "=l"(d) : "l"(a), "l"(b), "l"(c));
    return d;
}
__device__ __forceinline__ void unpack2(unsigned long long v, float& lo, float& hi) {
    asm("mov.b64 {%0, %1}, %2;" : "=f"(lo), "=f"(hi) : "l"(v));
}
__device__ __forceinline__ void cp16(uint32_t dst_smem, const void* src) {
    asm volatile("cp.async.cg.shared.global [%0], [%1], 16;" :: "r"(dst_smem), "l"(src));
}
__device__ __forceinline__ void cp_commit() { asm volatile("cp.async.commit_group;"); }
__device__ __forceinline__ void cp_wait0()  { asm volatile("cp.async.wait_group 0;"); }

// ============================================================================
// K0: prep — transpose W to [d][k], compute s2[k] sequentially (emulates
// XLA sum(W*W, axis=1): fp32 mul then fp32 add, d ascending), zero accums.
// grid: 8 x 128
// ============================================================================
__global__ void k0_prep(const float* __restrict__ W) {
    int k = blockIdx.x * 128 + threadIdx.x;      // 0..1023
    if (blockIdx.x == 0 && threadIdx.x == 0) g_loss_sum = 0.0f;
    if (k < KCODES) g_hist[k] = 0;
    float nrm = 0.0f;
    const float4* wr = reinterpret_cast<const float4*>(W + k * DIM);
#pragma unroll
    for (int i = 0; i < 16; i++) {
        float4 v = wr[i];
        nrm = __fadd_rn(nrm, __fmul_rn(v.x, v.x));
        nrm = __fadd_rn(nrm, __fmul_rn(v.y, v.y));
        nrm = __fadd_rn(nrm, __fmul_rn(v.z, v.z));
        nrm = __fadd_rn(nrm, __fmul_rn(v.w, v.w));
        g_wt[(i * 4 + 0) * KCODES + k] = v.x;
        g_wt[(i * 4 + 1) * KCODES + k] = v.y;
        g_wt[(i * 4 + 2) * KCODES + k] = v.z;
        g_wt[(i * 4 + 3) * KCODES + k] = v.w;
    }
    g_wnorm[k] = nrm;
}

// ============================================================================
// K1: fused (a) zero-fill of encodings region, (b) distance GEMM + argmin.
// Distances emulate the reference fp32 rounding:
//    d[n,k] = fsub( fadd(s1[n], s2[k]),  2 * dot(x_n, w_k) )
// with s1 computed as a sequential fp32 mul/add chain, dot via sequential-K
// fp32 FMA (f32x2 packed), strict-< first-index argmin.
// ============================================================================
#define ZBLOCKS 112
#define CBLOCKS 512
#define PTS_PER_BLK 128
#define KTILE 64
#define NKT (KCODES / KTILE)    // 16

// dynamic smem layout (bytes):
//   x4     [0,      32768)   : 128 pts x 64 d floats (permuted float4 layout)
//   w      [32768,  65536)   : 2 x (64 d x 64 codes) floats
//   wn     [65536,  66048)   : 2 x 64 floats
//   red_s  [66048,  70144)   : 8 x 128 floats
//   red_i  [70144,  74240)   : 8 x 128 ints
//   s1sm   [74240,  74752)   : 128 floats
#define K1_SMEM 74752

extern __shared__ char smem_raw[];

__global__ void __launch_bounds__(128) k1_argmin(const float* __restrict__ X,
                                                 float* __restrict__ out) {
    if (blockIdx.x < ZBLOCKS) {
        // ---- zero-fill encodings (268 MB) on the DRAM pipe ----
        float2* enc = reinterpret_cast<float2*>(out + OFF_ENC);   // 8B aligned
        const int nf2 = ENC_FLOATS / 2;
        const int stride = ZBLOCKS * 128;
        float2 z; z.x = 0.0f; z.y = 0.0f;
        for (int i = blockIdx.x * 128 + threadIdx.x; i < nf2; i += stride)
            enc[i] = z;
        return;
    }
    const int cb  = blockIdx.x - ZBLOCKS;       // 0..511
    const int tid = threadIdx.x;
    const int ptt = tid & 15;                    // point-thread  (x16 -> 128 pts)
    const int ct  = tid >> 4;                    // code-thread   (x8  -> 64 codes)

    float4* x4    = reinterpret_cast<float4*>(smem_raw);
    float*  wsm   = reinterpret_cast<float*>(smem_raw + 32768);
    float*  wnsm  = reinterpret_cast<float*>(smem_raw + 65536);
    float*  red_s = reinterpret_cast<float*>(smem_raw + 66048);
    int*    red_i = reinterpret_cast<int*>  (smem_raw + 70144);
    float*  s1sm  = reinterpret_cast<float*>(smem_raw + 74240);

    const int n0  = cb * PTS_PER_BLK;
    const int b   = n0 >> 12;                    // / 4096
    const int hw0 = n0 & 4095;
    const float* xbase = X + b * (DIM * HW) + hw0;

    uint32_t smem_base  = (uint32_t)__cvta_generic_to_shared(smem_raw);
    uint32_t w_sm_base  = smem_base + 32768;
    uint32_t wn_sm_base = smem_base + 65536;

    // prefetch W k-tile 0 into buffer 0
#pragma unroll
    for (int i = 0; i < 8; i++) {
        int lin = i * 128 + tid;                 // 0..1023
        int d = lin >> 4, seg = lin & 15;
        cp16(w_sm_base + (d * 64 + seg * 4) * 4, g_wt + d * KCODES + seg * 4);
    }
    if (tid < 16) cp16(wn_sm_base + tid * 16, g_wnorm + tid * 4);
    cp_commit();

    // load x tile (128 pts x 64 d) into permuted smem layout:
    // float4 of pts [j*4 .. j*4+3] for depth d lives at x4[d*32 + (j&1)*16 + (j>>1)]
    {
        int j = tid & 31, d0 = tid >> 5;
#pragma unroll
        for (int i = 0; i < 16; i++) {
            int d = d0 + i * 4;
            float4 v = *reinterpret_cast<const float4*>(xbase + d * HW + j * 4);
            x4[d * 32 + ((j & 1) * 16 + (j >> 1))] = v;
        }
    }
    __syncthreads();

    // s1[p] = sum_d x^2  — sequential fp32 mul/add chain, d ascending
    // (emulates XLA's sum(flat*flat, axis=1) rounding)
    {
        const int p = tid;                       // point 0..127
        const int perm = ((p >> 2) & 1) * 16 + (p >> 3);
        const int comp = p & 3;
        const float* xs = reinterpret_cast<const float*>(x4);
        float s1 = 0.0f;
#pragma unroll
        for (int d = 0; d < DIM; d++) {
            float xv = xs[(d * 32 + perm) * 4 + comp];
            s1 = __fadd_rn(s1, __fmul_rn(xv, xv));
        }
        s1sm[p] = s1;
    }
    cp_wait0();
    __syncthreads();

    float s1p[8];
#pragma unroll
    for (int p = 0; p < 8; p++) s1p[p] = s1sm[ptt * 8 + p];

    unsigned long long acc[8][4];
    float best[8];
    int   bidx[8];
#pragma unroll
    for (int p = 0; p < 8; p++) { best[p] = 3.4e38f; bidx[p] = 0; }

    for (int kt = 0; kt < NKT; kt++) {
        const int buf = kt & 1;
        if (kt + 1 < NKT) {
            const int k0n = (kt + 1) * KTILE;
            const int nb  = buf ^ 1;
#pragma unroll
            for (int i = 0; i < 8; i++) {
                int lin = i * 128 + tid;
                int d = lin >> 4, seg = lin & 15;
                cp16(w_sm_base + (nb * 4096 + d * 64 + seg * 4) * 4,
                     g_wt + d * KCODES + k0n + seg * 4);
            }
            if (tid < 16) cp16(wn_sm_base + (nb * 64 + tid * 4) * 4, g_wnorm + k0n + tid * 4);
            cp_commit();
        }

#pragma unroll
        for (int p = 0; p < 8; p++)
#pragma unroll
            for (int q = 0; q < 4; q++) acc[p][q] = 0ull;

        const ulonglong2* w2 = reinterpret_cast<const ulonglong2*>(wsm + buf * 4096);

#pragma unroll 4
        for (int d = 0; d < DIM; d++) {
            float4 xa = x4[d * 32 + ptt];         // pts ptt*8 + 0..3
            float4 xb = x4[d * 32 + 16 + ptt];    // pts ptt*8 + 4..7
            unsigned long long px[8];
            px[0] = pack2(xa.x); px[1] = pack2(xa.y); px[2] = pack2(xa.z); px[3] = pack2(xa.w);
            px[4] = pack2(xb.x); px[5] = pack2(xb.y); px[6] = pack2(xb.z); px[7] = pack2(xb.w);
            ulonglong2 wA = w2[d * 16 + ct * 2];       // codes c0+0..3 (2 f32x2)
            ulonglong2 wB = w2[d * 16 + ct * 2 + 1];   // codes c0+4..7
#pragma unroll
            for (int p = 0; p < 8; p++) {
                acc[p][0] = fma2(px[p], wA.x, acc[p][0]);
                acc[p][1] = fma2(px[p], wA.y, acc[p][1]);
                acc[p][2] = fma2(px[p], wB.x, acc[p][2]);
                acc[p][3] = fma2(px[p], wB.y, acc[p][3]);
            }
        }

        // emulated reference distances: d = (s1 + s2) - 2*dot, each op fp32-rounded
        const int kbase = kt * KTILE + ct * 8;
#pragma unroll
        for (int p = 0; p < 8; p++) {
#pragma unroll
            for (int q = 0; q < 4; q++) {
                float lo, hi; unpack2(acc[p][q], lo, hi);
                float w0 = wnsm[buf * 64 + ct * 8 + 2 * q];
                float w1 = wnsm[buf * 64 + ct * 8 + 2 * q + 1];
                float e0 = __fsub_rn(__fadd_rn(s1p[p], w0), __fmul_rn(2.0f, lo));
                float e1 = __fsub_rn(__fadd_rn(s1p[p], w1), __fmul_rn(2.0f, hi));
                if (e0 < best[p]) { best[p] = e0; bidx[p] = kbase + 2 * q; }
                if (e1 < best[p]) { best[p] = e1; bidx[p] = kbase + 2 * q + 1; }
            }
        }

        if (kt + 1 < NKT) cp_wait0();
        __syncthreads();
    }

    // cross code-thread reduction: pick (min value, then min index) == first-min
#pragma unroll
    for (int p = 0; p < 8; p++) {
        red_s[ct * 128 + ptt * 8 + p] = best[p];
        red_i[ct * 128 + ptt * 8 + p] = bidx[p];
    }
    __syncthreads();
    {
        int p = tid;                              // 0..127 -> point n0 + p
        float bs = red_s[p];
        int   bi = red_i[p];
#pragma unroll
        for (int c = 1; c < 8; c++) {
            float s = red_s[c * 128 + p];
            int   i2 = red_i[c * 128 + p];
            if (s < bs || (s == bs && i2 < bi)) { bs = s; bi = i2; }
        }
        g_idx[n0 + p] = bi;
    }
}

// ============================================================================
// K2: epilogue — quantized_st gather-write (NCHW, emulated x+(q-x)),
// encodings ones, histogram, loss sum
// grid: 4096 x 256 ; one thread per 4 consecutive hw elements of one channel
// ============================================================================
__global__ void k2_scatter(const float* __restrict__ X,
                           const float* __restrict__ W,
                           float* __restrict__ out) {
    const int tid = threadIdx.x;
    const int e4  = blockIdx.x * 256 + tid;      // 0 .. 1,048,575
    const int b   = e4 >> 16;
    const int c   = (e4 >> 10) & 63;
    const int hw4 = e4 & 1023;
    const int n0  = b * HW + hw4 * 4;

    const int4 id = *reinterpret_cast<const int4*>(g_idx + n0);
    float q0 = __ldg(W + id.x * DIM + c);
    float q1 = __ldg(W + id.y * DIM + c);
    float q2 = __ldg(W + id.z * DIM + c);
    float q3 = __ldg(W + id.w * DIM + c);

    const int off = (b * DIM + c) * HW + hw4 * 4;
    float4 xv = *reinterpret_cast<const float4*>(X + off);

    float d0 = __fsub_rn(q0, xv.x);
    float d1 = __fsub_rn(q1, xv.y);
    float d2 = __fsub_rn(q2, xv.z);
    float d3 = __fsub_rn(q3, xv.w);

    // straight-through estimator value: x + (q - x), rounded like the reference
    float* oq = out + OFF_Q + off;               // 4B aligned only
    oq[0] = __fadd_rn(xv.x, d0);
    oq[1] = __fadd_rn(xv.y, d1);
    oq[2] = __fadd_rn(xv.z, d2);
    oq[3] = __fadd_rn(xv.w, d3);

    float ls = d0 * d0 + d1 * d1 + d2 * d2 + d3 * d3;

    // block reduction of loss partial
#pragma unroll
    for (int s = 16; s > 0; s >>= 1) ls += __shfl_xor_sync(0xffffffffu, ls, s);
    __shared__ float wsum[8];
    if ((tid & 31) == 0) wsum[tid >> 5] = ls;
    __syncthreads();
    if (tid == 0) {
        float s = 0.0f;
#pragma unroll
        for (int w = 0; w < 8; w++) s += wsum[w];
        atomicAdd(&g_loss_sum, s);
    }

    // one-hot writes + histogram (first 65536 threads, one per point)
    if (e4 < N_PTS) {
        int n  = e4;
        int id1 = g_idx[n];
        out[OFF_ENC + n * KCODES + id1] = 1.0f;
        atomicAdd(&g_hist[id1], 1);
    }
}

// ============================================================================
// K3: finalize loss + perplexity (1 block x 1024)
// ============================================================================
__global__ void k3_final(float* __restrict__ out) {
    __shared__ float red[32];
    const int t = threadIdx.x;
    float p = (float)g_hist[t] * (1.0f / (float)N_PTS);
    float v = p * logf(p + 1e-10f);
#pragma unroll
    for (int s = 16; s > 0; s >>= 1) v += __shfl_xor_sync(0xffffffffu, v, s);
    if ((t & 31) == 0) red[t >> 5] = v;
    __syncthreads();
    if (t < 32) {
        float s = red[t];
#pragma unroll
        for (int sh = 16; sh > 0; sh >>= 1) s += __shfl_xor_sync(0xffffffffu, s, sh);
        if (t == 0) {
            out[OFF_PERP] = expf(-s);
            out[OFF_LOSS] = 1.25f * g_loss_sum * (1.0f / (float)NELEM);
        }
    }
}

// ============================================================================
extern "C" void kernel_launch(void* const* d_in, const int* in_sizes, int n_in,
                              void* d_out, int out_size) {
    const float* X = (const float*)d_in[0];
    const float* W = (const float*)d_in[1];
    if (n_in >= 2 && in_sizes[0] == KCODES * DIM && in_sizes[1] == NELEM) {
        // defensive: swap if metadata order is (W, inputs)
        const float* t = X; X = W; W = t;
    }
    float* out = (float*)d_out;

    cudaFuncSetAttribute(k1_argmin, cudaFuncAttributeMaxDynamicSharedMemorySize, K1_SMEM);

    k0_prep<<<8, 128>>>(W);
    k1_argmin<<<ZBLOCKS + CBLOCKS, 128, K1_SMEM>>>(X, out);
    k2_scatter<<<4096, 256>>>(X, W, out);
    k3_final<<<1, 1024>>>(out);
}

// round 4
// speedup vs baseline: 1.7673x; 1.7673x over previous
#include <cuda_runtime.h>
#include <cstdint>
#include <math.h>

// ---------------- problem constants ----------------
#define N_PTS   65536            // 16 * 64 * 64 points
#define KCODES  1024
#define DIM     64
#define NELEM   4194304          // 16*64*64*64
#define HW      4096             // 64*64

// output layout: loss | quantized_st (NCHW) | perplexity | encodings [N, K]
#define OFF_LOSS 0
#define OFF_Q    1
#define OFF_PERP (1 + NELEM)
#define OFF_ENC  (OFF_PERP + 1)

// ---------------- schedule ----------------
#define GRID      304            // 2 blocks/SM x 152 SMs -> single wave
#define TILE_PTS  64
#define NTILES    (N_PTS / TILE_PTS)   // 1024
#define KT        128
#define NKT       (KCODES / KT)        // 8

// ---------------- smem layout (bytes) ----------------
#define SM_X    0                // 64 pts x 64 d floats        (16384)
#define SM_W    16384            // 2 x (64 d x 128 c) floats   (65536)
#define SM_WN   81920            // 2 x 128 floats              (1024)
#define SM_S1   82944            // 64 floats                   (256)
#define SM_BI   83200            // 64 ints                     (256)
#define SM_RS   83456            // 16 x 64 floats              (4096)
#define SM_RI   87552            // 16 x 64 ints                (4096)
#define SM_TOT  91648

// ---------------- device scratch ----------------
__device__ __align__(16) float g_wt[DIM * KCODES];   // wt[d*1024 + k]
__device__ __align__(16) float g_wnorm[KCODES];
__device__ float g_loss_sum;
__device__ int   g_hist[KCODES];
__device__ int   g_done;

// ---------------- helpers ----------------
__device__ __forceinline__ unsigned long long pack2(float v) {
    unsigned long long r;
    asm("mov.b64 %0, {%1, %1};" : "=l"(r) : "f"(v));
    return r;
}
__device__ __forceinline__ unsigned long long fma2(unsigned long long a,
                                                   unsigned long long b,
                                                   unsigned long long c) {
    unsigned long long d;
    asm("fma.rn.f32x2 %0, %1, %2, %3;" : "=l"(d) : "l"(a), "l"(b), "l"(c));
    return d;
}
__device__ __forceinline__ void unpack2(unsigned long long v, float& lo, float& hi) {
    asm("mov.b64 {%0, %1}, %2;" : "=f"(lo), "=f"(hi) : "l"(v));
}
__device__ __forceinline__ void cp16(uint32_t dst_smem, const void* src) {
    asm volatile("cp.async.cg.shared.global [%0], [%1], 16;" :: "r"(dst_smem), "l"(src));
}
__device__ __forceinline__ void cp_commit() { asm volatile("cp.async.commit_group;"); }
__device__ __forceinline__ void cp_wait0()  { asm volatile("cp.async.wait_group 0;"); }

// ============================================================================
// K0: transpose W -> g_wt[d][k], s2[k] via sequential fp32 mul/add (reference
// rounding emulation), reset accumulators.  grid: 8 x 128
// ============================================================================
__global__ void k0_prep(const float* __restrict__ W) {
    int k = blockIdx.x * 128 + threadIdx.x;      // 0..1023
    if (blockIdx.x == 0 && threadIdx.x == 0) { g_loss_sum = 0.0f; g_done = 0; }
    g_hist[k] = 0;
    float nrm = 0.0f;
    const float4* wr = reinterpret_cast<const float4*>(W + k * DIM);
#pragma unroll
    for (int i = 0; i < 16; i++) {
        float4 v = wr[i];
        nrm = __fadd_rn(nrm, __fmul_rn(v.x, v.x));
        nrm = __fadd_rn(nrm, __fmul_rn(v.y, v.y));
        nrm = __fadd_rn(nrm, __fmul_rn(v.z, v.z));
        nrm = __fadd_rn(nrm, __fmul_rn(v.w, v.w));
        g_wt[(i * 4 + 0) * KCODES + k] = v.x;
        g_wt[(i * 4 + 1) * KCODES + k] = v.y;
        g_wt[(i * 4 + 2) * KCODES + k] = v.z;
        g_wt[(i * 4 + 3) * KCODES + k] = v.w;
    }
    g_wnorm[k] = nrm;
}

// ============================================================================
// K1: persistent fused kernel. Per 64-pt tile: distance GEMM (exact reference
// rounding) + argmin + zero-fill of this tile's encoding rows + one-hot +
// histogram + quantized_st + loss partial. Last block finalizes loss/perp.
// ============================================================================
extern __shared__ char smem_raw[];

__global__ void __launch_bounds__(128) k1_main(const float* __restrict__ X,
                                               const float* __restrict__ Wp,
                                               float* __restrict__ out) {
    const int tid = threadIdx.x;
    const int ptt = tid & 7;                     // 8 pt-threads -> 64 pts
    const int ct  = tid >> 3;                    // 16 code-threads -> 128 codes/kt

    float4* x4w   = reinterpret_cast<float4*>(smem_raw + SM_X);
    const float* xs = reinterpret_cast<const float*>(smem_raw + SM_X);
    float*  wnsm  = reinterpret_cast<float*>(smem_raw + SM_WN);
    float*  s1sm  = reinterpret_cast<float*>(smem_raw + SM_S1);
    int*    bidx_sm = reinterpret_cast<int*>(smem_raw + SM_BI);
    float*  red_s = reinterpret_cast<float*>(smem_raw + SM_RS);
    int*    red_i = reinterpret_cast<int*>  (smem_raw + SM_RI);

    uint32_t smem_base = (uint32_t)__cvta_generic_to_shared(smem_raw);
    uint32_t w_sm  = smem_base + SM_W;
    uint32_t wn_sm = smem_base + SM_WN;

    float ls_acc = 0.0f;

    for (int t = blockIdx.x; t < NTILES; t += GRID) {
        const int n0  = t * TILE_PTS;
        const int b   = n0 >> 12;
        const int hw0 = n0 & 4095;

        __syncthreads();   // protect x/red smem from previous tile's readers

        // prefetch W k-tile 0 -> buffer 0 (16 cp16/thread) + wn
#pragma unroll
        for (int i = 0; i < 16; i++) {
            int lin = i * 128 + tid;             // 0..2047
            int d = lin >> 5, seg = lin & 31;
            cp16(w_sm + d * 512 + seg * 16, g_wt + d * KCODES + seg * 4);
        }
        if (tid < 32) cp16(wn_sm + tid * 16, g_wnorm + tid * 4);
        cp_commit();

        // load x tile: 64 pts x 64 d, group-interleaved so compute reads are
        // conflict-free: float4 j of dim d -> slot (j even: j/2, j odd: 8+j/2)
        {
            int j = tid & 15, d0 = tid >> 4;     // j: float4 within d, d0: 0..7
            const float* xb = X + (size_t)b * (DIM * HW) + hw0;
#pragma unroll
            for (int i = 0; i < 8; i++) {
                int d = d0 + i * 8;
                float4 v = *reinterpret_cast<const float4*>(xb + d * HW + j * 4);
                x4w[d * 16 + ((j & 1) ? (8 + (j >> 1)) : (j >> 1))] = v;
            }
        }
        __syncthreads();

        // s1[p]: sequential fp32 mul/add over d ascending (reference emulation)
        if (tid < 64) {
            int p = tid, r = p & 7;
            int xoff = ((r < 4) ? (p >> 3) : (8 + (p >> 3))) * 4 + (p & 3);
            float s1 = 0.0f;
#pragma unroll
            for (int d = 0; d < DIM; d++)
                s1 = __fadd_rn(s1, __fmul_rn(xs[d * 64 + xoff], xs[d * 64 + xoff]));
            s1sm[p] = s1;
        }
        cp_wait0();
        __syncthreads();

        float s1p[8];
#pragma unroll
        for (int p = 0; p < 8; p++) s1p[p] = s1sm[ptt * 8 + p];

        float best[8];
        int   bidx[8];
#pragma unroll
        for (int p = 0; p < 8; p++) { best[p] = 3.4e38f; bidx[p] = 0; }

        for (int kt = 0; kt < NKT; kt++) {
            const int buf = kt & 1;
            if (kt + 1 < NKT) {
                const int kb = (kt + 1) * KT;
                const int nb = buf ^ 1;
#pragma unroll
                for (int i = 0; i < 16; i++) {
                    int lin = i * 128 + tid;
                    int d = lin >> 5, seg = lin & 31;
                    cp16(w_sm + nb * 32768 + d * 512 + seg * 16,
                         g_wt + d * KCODES + kb + seg * 4);
                }
                if (tid < 32) cp16(wn_sm + nb * 512 + tid * 16, g_wnorm + kb + tid * 4);
                cp_commit();
            }

            // zero-fill this tile's slice of encodings (overlaps FMA on DRAM pipe)
            {
                float2 z; z.x = 0.0f; z.y = 0.0f;
                float2* enc2 = reinterpret_cast<float2*>(out + OFF_ENC) + (size_t)n0 * 512;
                int base = kt * 4096 + tid;
#pragma unroll
                for (int s = 0; s < 32; s++) enc2[base + s * 128] = z;
            }

            unsigned long long acc[8][4];
#pragma unroll
            for (int p = 0; p < 8; p++)
#pragma unroll
                for (int q = 0; q < 4; q++) acc[p][q] = 0ull;

            const ulonglong2* w2 =
                reinterpret_cast<const ulonglong2*>(smem_raw + SM_W + buf * 32768);
            const float4* x4 = reinterpret_cast<const float4*>(smem_raw + SM_X);

#pragma unroll 4
            for (int d = 0; d < DIM; d++) {
                float4 xa = x4[d * 16 + ptt];          // pts ptt*8+0..3
                float4 xb = x4[d * 16 + 8 + ptt];      // pts ptt*8+4..7
                unsigned long long px[8];
                px[0] = pack2(xa.x); px[1] = pack2(xa.y);
                px[2] = pack2(xa.z); px[3] = pack2(xa.w);
                px[4] = pack2(xb.x); px[5] = pack2(xb.y);
                px[6] = pack2(xb.z); px[7] = pack2(xb.w);
                ulonglong2 wA = w2[d * 32 + ct * 2];       // codes ct*8+0..3
                ulonglong2 wB = w2[d * 32 + ct * 2 + 1];   // codes ct*8+4..7
#pragma unroll
                for (int p = 0; p < 8; p++) {
                    acc[p][0] = fma2(px[p], wA.x, acc[p][0]);
                    acc[p][1] = fma2(px[p], wA.y, acc[p][1]);
                    acc[p][2] = fma2(px[p], wB.x, acc[p][2]);
                    acc[p][3] = fma2(px[p], wB.y, acc[p][3]);
                }
            }

            // d = fsub(fadd(s1, s2), 2*dot) — reference rounding; strict-< argmin
            const int kbase = kt * KT + ct * 8;
#pragma unroll
            for (int p = 0; p < 8; p++) {
#pragma unroll
                for (int q = 0; q < 4; q++) {
                    float lo, hi; unpack2(acc[p][q], lo, hi);
                    float w0 = wnsm[buf * 128 + ct * 8 + 2 * q];
                    float w1 = wnsm[buf * 128 + ct * 8 + 2 * q + 1];
                    float e0 = __fsub_rn(__fadd_rn(s1p[p], w0), __fmul_rn(2.0f, lo));
                    float e1 = __fsub_rn(__fadd_rn(s1p[p], w1), __fmul_rn(2.0f, hi));
                    if (e0 < best[p]) { best[p] = e0; bidx[p] = kbase + 2 * q; }
                    if (e1 < best[p]) { best[p] = e1; bidx[p] = kbase + 2 * q + 1; }
                }
            }

            if (kt + 1 < NKT) cp_wait0();
            __syncthreads();
        }

        // cross-ct reduction (16 candidates/pt): min value then min index
#pragma unroll
        for (int p = 0; p < 8; p++) {
            red_s[ct * 64 + ptt * 8 + p] = best[p];
            red_i[ct * 64 + ptt * 8 + p] = bidx[p];
        }
        __syncthreads();
        if (tid < 64) {
            float bs = red_s[tid];
            int   bi = red_i[tid];
#pragma unroll
            for (int c = 1; c < 16; c++) {
                float s = red_s[c * 64 + tid];
                int   i2 = red_i[c * 64 + tid];
                if (s < bs || (s == bs && i2 < bi)) { bs = s; bi = i2; }
            }
            bidx_sm[tid] = bi;
            atomicAdd(&g_hist[bi], 1);
            // zero-fill of this row finished last kt; sync above orders it
            out[(size_t)OFF_ENC + (size_t)(n0 + tid) * KCODES + bi] = 1.0f;
        }
        __syncthreads();

        // quantized_st = fadd(x, fsub(q, x))  (reference STE rounding) + loss
        {
            int p = tid & 63, half = tid >> 6;
            int r = p & 7;
            int xoff = ((r < 4) ? (p >> 3) : (8 + (p >> 3))) * 4 + (p & 3);
            int bi = bidx_sm[p];
            const float4* wrow =
                reinterpret_cast<const float4*>(Wp + bi * DIM) + half * 8;
            float* oq = out + OFF_Q + (size_t)b * (DIM * HW) + hw0 + p;
#pragma unroll
            for (int i = 0; i < 8; i++) {
                float4 qv = wrow[i];
                int c0 = half * 32 + i * 4;
                float x0 = xs[(c0 + 0) * 64 + xoff];
                float x1 = xs[(c0 + 1) * 64 + xoff];
                float x2 = xs[(c0 + 2) * 64 + xoff];
                float x3 = xs[(c0 + 3) * 64 + xoff];
                float d0 = __fsub_rn(qv.x, x0);
                float d1 = __fsub_rn(qv.y, x1);
                float d2 = __fsub_rn(qv.z, x2);
                float d3 = __fsub_rn(qv.w, x3);
                oq[(size_t)(c0 + 0) * HW] = __fadd_rn(x0, d0);
                oq[(size_t)(c0 + 1) * HW] = __fadd_rn(x1, d1);
                oq[(size_t)(c0 + 2) * HW] = __fadd_rn(x2, d2);
                oq[(size_t)(c0 + 3) * HW] = __fadd_rn(x3, d3);
                ls_acc += d0 * d0 + d1 * d1 + d2 * d2 + d3 * d3;
            }
        }
    }

    // ---- block loss reduce + completion ticket ----
    __shared__ float wsum[4];
    __shared__ int is_last;
#pragma unroll
    for (int s = 16; s > 0; s >>= 1) ls_acc += __shfl_xor_sync(0xffffffffu, ls_acc, s);
    if ((tid & 31) == 0) wsum[tid >> 5] = ls_acc;
    __syncthreads();
    if (tid == 0) {
        float s = wsum[0] + wsum[1] + wsum[2] + wsum[3];
        atomicAdd(&g_loss_sum, s);
        __threadfence();
        is_last = (atomicAdd(&g_done, 1) == GRID - 1) ? 1 : 0;
    }
    __syncthreads();

    if (is_last) {
        // finale: perplexity + loss
        float v = 0.0f;
#pragma unroll
        for (int i = 0; i < 8; i++) {
            int c = tid + 128 * i;
            float p = (float)__ldcg(&g_hist[c]) * (1.0f / (float)N_PTS);
            v += p * logf(p + 1e-10f);
        }
#pragma unroll
        for (int s = 16; s > 0; s >>= 1) v += __shfl_xor_sync(0xffffffffu, v, s);
        __shared__ float fin[4];
        if ((tid & 31) == 0) fin[tid >> 5] = v;
        __syncthreads();
        if (tid == 0) {
            float s = fin[0] + fin[1] + fin[2] + fin[3];
            out[OFF_PERP] = expf(-s);
            out[OFF_LOSS] = 1.25f * __ldcg(&g_loss_sum) * (1.0f / (float)NELEM);
        }
    }
}

// ============================================================================
extern "C" void kernel_launch(void* const* d_in, const int* in_sizes, int n_in,
                              void* d_out, int out_size) {
    const float* X = (const float*)d_in[0];
    const float* W = (const float*)d_in[1];
    if (n_in >= 2 && in_sizes[0] == KCODES * DIM && in_sizes[1] == NELEM) {
        const float* t = X; X = W; W = t;   // defensive order swap
    }
    float* out = (float*)d_out;

    cudaFuncSetAttribute(k1_main, cudaFuncAttributeMaxDynamicSharedMemorySize, SM_TOT);

    k0_prep<<<8, 128>>>(W);
    k1_main<<<GRID, 128, SM_TOT>>>(X, W, out);
}